// round 3
// baseline (speedup 1.0000x reference)
#include <cuda_runtime.h>

// LIF scan: x [B, T, N] -> spikes [B, T, N]
//   mem = TAU*mem + x;  spike = (mem > V_TH);  mem = spike ? 0 : mem
// Parallel over (B, N); sequential over T in registers.
// float2 per thread -> 262144 threads (occ ~86%) for deeper DRAM MLP.

#define B_DIM 64
#define T_DIM 128
#define N_DIM 8192

__global__ void __launch_bounds__(256) lif_kernel(const float2* __restrict__ x,
                                                  float2* __restrict__ out) {
    const float V_TH = 1.0f;
    const float TAU  = 0.25f;

    const int n2_per_b = N_DIM / 2;                    // 4096 float2 per time-row
    int tid = blockIdx.x * blockDim.x + threadIdx.x;   // 0 .. B*N/2-1
    int b   = tid >> 12;                               // tid / 4096
    int n2  = tid & (n2_per_b - 1);

    // base index (in float2 units) of x[b, 0, n2*2]
    long base = (long)b * T_DIM * n2_per_b + n2;

    float mx = 0.0f, my = 0.0f;

#pragma unroll 8
    for (int t = 0; t < T_DIM; ++t) {
        long idx = base + (long)t * n2_per_b;
        float2 v = __ldcs(&x[idx]);          // streaming load (touched once)

        mx = TAU * mx + v.x;
        my = TAU * my + v.y;

        float sx = (mx > V_TH) ? 1.0f : 0.0f;
        float sy = (my > V_TH) ? 1.0f : 0.0f;

        mx = (sx > 0.0f) ? 0.0f : mx;
        my = (sy > 0.0f) ? 0.0f : my;

        float2 s = make_float2(sx, sy);
        __stcs(&out[idx], s);                // streaming store
    }
}

extern "C" void kernel_launch(void* const* d_in, const int* in_sizes, int n_in,
                              void* d_out, int out_size) {
    const float2* x = (const float2*)d_in[0];
    float2* out     = (float2*)d_out;

    int total_threads = B_DIM * (N_DIM / 2);   // 262144
    int block = 256;
    int grid  = total_threads / block;         // 1024
    lif_kernel<<<grid, block>>>(x, out);
}

// round 4
// speedup vs baseline: 1.1338x; 1.1338x over previous
#include <cuda_runtime.h>

// LIF scan: x [B, T, N] -> spikes [B, T, N]
//   mem = TAU*mem + x;  spike = (mem > V_TH);  mem = spike ? 0 : mem
// float4 per thread (128-bit LDG/STG), deep unroll for load batching (MLP).

#define B_DIM 64
#define T_DIM 128
#define N_DIM 8192

__global__ void __launch_bounds__(128) lif_kernel(const float4* __restrict__ x,
                                                  float4* __restrict__ out) {
    const float V_TH = 1.0f;
    const float TAU  = 0.25f;

    const int n4_per_b = N_DIM / 4;                    // 2048 float4 per time-row
    int tid = blockIdx.x * blockDim.x + threadIdx.x;   // 0 .. B*N/4-1
    int b   = tid >> 11;                               // / 2048
    int n4  = tid & (n4_per_b - 1);

    long base = (long)b * T_DIM * n4_per_b + n4;

    float mx = 0.f, my = 0.f, mz = 0.f, mw = 0.f;

    // T = 128 = 8 chunks of 16. Within a chunk, batch all 16 loads up front
    // (addresses are independent of the recurrence), then run the serial
    // LIF update and the 16 stores.
    const int U = 16;
#pragma unroll 1
    for (int tc = 0; tc < T_DIM; tc += U) {
        float4 v[U];
#pragma unroll
        for (int u = 0; u < U; ++u)
            v[u] = x[base + (long)(tc + u) * n4_per_b];

        float4 s[U];
#pragma unroll
        for (int u = 0; u < U; ++u) {
            mx = TAU * mx + v[u].x;
            my = TAU * my + v[u].y;
            mz = TAU * mz + v[u].z;
            mw = TAU * mw + v[u].w;

            s[u].x = (mx > V_TH) ? 1.0f : 0.0f;
            s[u].y = (my > V_TH) ? 1.0f : 0.0f;
            s[u].z = (mz > V_TH) ? 1.0f : 0.0f;
            s[u].w = (mw > V_TH) ? 1.0f : 0.0f;

            mx = (s[u].x > 0.0f) ? 0.0f : mx;
            my = (s[u].y > 0.0f) ? 0.0f : my;
            mz = (s[u].z > 0.0f) ? 0.0f : mz;
            mw = (s[u].w > 0.0f) ? 0.0f : mw;
        }

#pragma unroll
        for (int u = 0; u < U; ++u)
            out[base + (long)(tc + u) * n4_per_b] = s[u];
    }
}

extern "C" void kernel_launch(void* const* d_in, const int* in_sizes, int n_in,
                              void* d_out, int out_size) {
    const float4* x = (const float4*)d_in[0];
    float4* out     = (float4*)d_out;

    int total_threads = B_DIM * (N_DIM / 4);   // 131072
    int block = 128;
    int grid  = total_threads / block;         // 1024
    lif_kernel<<<grid, block>>>(x, out);
}

// round 5
// speedup vs baseline: 1.1382x; 1.0039x over previous
#include <cuda_runtime.h>

// LIF scan: x [B, T, N] -> spikes [B, T, N]
//   mem = TAU*mem + x;  spike = (mem > V_TH);  mem = spike ? 0 : mem
// float4 per thread. 16-deep load batches FORCED via asm memory barrier so
// ptxas cannot re-fuse into load->consume->store trickle. Register budget
// granted via __launch_bounds__(128, 5) (<=102 regs, >=20 warps/SM).

#define B_DIM 64
#define T_DIM 128
#define N_DIM 8192

__global__ void __launch_bounds__(128, 5) lif_kernel(const float4* __restrict__ x,
                                                     float4* __restrict__ out) {
    const float V_TH = 1.0f;
    const float TAU  = 0.25f;

    const int n4_per_b = N_DIM / 4;                    // 2048 float4 per time-row
    int tid = blockIdx.x * blockDim.x + threadIdx.x;   // 0 .. B*N/4-1
    int b   = tid >> 11;                               // / 2048
    int n4  = tid & (n4_per_b - 1);

    long base = (long)b * T_DIM * n4_per_b + n4;

    float mx = 0.f, my = 0.f, mz = 0.f, mw = 0.f;

    const int U = 16;                                  // 8 chunks of 16 t-steps
#pragma unroll 1
    for (int tc = 0; tc < T_DIM; tc += U) {
        float4 v[U];
#pragma unroll
        for (int u = 0; u < U; ++u)
            v[u] = x[base + (long)(tc + u) * n4_per_b];

        // Compiler barrier: all 16 LDG.128s must issue before any STG below.
        asm volatile("" ::: "memory");

#pragma unroll
        for (int u = 0; u < U; ++u) {
            mx = TAU * mx + v[u].x;
            my = TAU * my + v[u].y;
            mz = TAU * mz + v[u].z;
            mw = TAU * mw + v[u].w;

            float4 s;
            s.x = (mx > V_TH) ? 1.0f : 0.0f;
            s.y = (my > V_TH) ? 1.0f : 0.0f;
            s.z = (mz > V_TH) ? 1.0f : 0.0f;
            s.w = (mw > V_TH) ? 1.0f : 0.0f;

            mx = (s.x > 0.0f) ? 0.0f : mx;
            my = (s.y > 0.0f) ? 0.0f : my;
            mz = (s.z > 0.0f) ? 0.0f : mz;
            mw = (s.w > 0.0f) ? 0.0f : mw;

            out[base + (long)(tc + u) * n4_per_b] = s;
        }
    }
}

extern "C" void kernel_launch(void* const* d_in, const int* in_sizes, int n_in,
                              void* d_out, int out_size) {
    const float4* x = (const float4*)d_in[0];
    float4* out     = (float4*)d_out;

    int total_threads = B_DIM * (N_DIM / 4);   // 131072
    int block = 128;
    int grid  = total_threads / block;         // 1024
    lif_kernel<<<grid, block>>>(x, out);
}